// round 16
// baseline (speedup 1.0000x reference)
#include <cuda_runtime.h>
#include <cuda_fp16.h>
#include <cstdint>
#include <cstddef>

// ---------------- problem constants ----------------
#define BATCH   4096
#define HALF_B  2048
#define NTAB    26
#define DEMB    128
#define NTPER   81920
#define EROWS   100000
#define FIN     3456
#define LOWR    512
#define STAGES  3

// ---------------- scratch (device globals; no runtime alloc) ----------------
__device__ float  g_comb[BATCH * FIN];     // combined features (fp32, immutable)
__device__ float  g_xl  [BATCH * FIN];     // DCN running state (fp32 master)
__device__ int    g_is64;
__device__ __half g_actA[BATCH * FIN];     // fp16 copy of current DCN input
__device__ __half g_z0h [BATCH * 1024];    // also bot0h (disjoint in time)
__device__ __half g_z1h [BATCH * 1024];    // also bot1h
__device__ __half g_xvh [BATCH * LOWR];
// dedicated fp16 weight buffers
__device__ __half g_wV [3 * LOWR * FIN];
__device__ __half g_wW [3 * FIN * LOWR];
__device__ __half g_wT0[1024 * FIN];
__device__ __half g_wT1[1024 * 1024];
__device__ __half g_wT2[512 * 1024];
__device__ __half g_wB1[256 * 512];
__device__ __half g_wB2[128 * 256];

// ==================== PTX helpers ====================
__device__ __forceinline__ uint32_t smem_u32(const void* p) {
    uint32_t a;
    asm("{ .reg .u64 t; cvta.to.shared.u64 t, %1; cvt.u32.u64 %0, t; }" : "=r"(a) : "l"(p));
    return a;
}
#define SWZ(x) ((x) ^ (((x) >> 3) & 0x70))

__device__ __forceinline__ void cp16(uint32_t dst, const void* src) {
    asm volatile("cp.async.cg.shared.global [%0], [%1], 16;" :: "r"(dst), "l"(src) : "memory");
}
__device__ __forceinline__ void cp_commit() { asm volatile("cp.async.commit_group;" ::: "memory"); }
template<int N> __device__ __forceinline__ void cp_wait() {
    asm volatile("cp.async.wait_group %0;" :: "n"(N) : "memory");
}
__device__ __forceinline__ void ldm_x4(uint32_t& r0, uint32_t& r1, uint32_t& r2, uint32_t& r3,
                                       uint32_t addr) {
    asm volatile("ldmatrix.sync.aligned.m8n8.x4.shared.b16 {%0,%1,%2,%3}, [%4];"
                 : "=r"(r0), "=r"(r1), "=r"(r2), "=r"(r3) : "r"(addr));
}
__device__ __forceinline__ void mma16816(float* c, const uint32_t* a, uint32_t b0, uint32_t b1) {
    asm volatile(
        "mma.sync.aligned.m16n8k16.row.col.f32.f16.f16.f32 "
        "{%0,%1,%2,%3}, {%4,%5,%6,%7}, {%8,%9}, {%0,%1,%2,%3};"
        : "+f"(c[0]), "+f"(c[1]), "+f"(c[2]), "+f"(c[3])
        : "r"(a[0]), "r"(a[1]), "r"(a[2]), "r"(a[3]), "r"(b0), "r"(b1));
}

__device__ __forceinline__ void half_store2(__half* __restrict__ p, size_t o,
                                            float v0, float v1) {
    __half2 hh; hh.x = __float2half_rn(v0); hh.y = __float2half_rn(v1);
    *(__half2*)(p + o) = hh;
}

// ==================== dtype detection (int64 vs int32) ====================
__global__ void detect_kernel(const unsigned* __restrict__ words, int n_elems) {
    __shared__ unsigned red;
    if (threadIdx.x == 0) red = 0u;
    __syncthreads();
    int n = n_elems < 8192 ? n_elems : 8192;
    unsigned acc = 0u;
    for (int i = 1 + 2 * (int)threadIdx.x; i < n; i += 2 * (int)blockDim.x) acc |= words[i];
    if (acc) atomicOr(&red, 1u);
    __syncthreads();
    if (threadIdx.x == 0) g_is64 = (red == 0u) ? 1 : 0;
}

// ==================== fused weight conversion + out-init ===================
struct ConvArgs {
    const float* src[7];
    __half*      dst[7];
    int          n[7];
    int          total;
    float*       out;       // d_out, init to b3[0]
    const float* b3;
};

__global__ void conv_kernel(ConvArgs a) {
    if (blockIdx.x == 0) {   // init final output to bias b3
        float b = a.b3[0];
        for (int i = threadIdx.x; i < BATCH; i += blockDim.x) a.out[i] = b;
    }
    for (int gid = blockIdx.x * blockDim.x + threadIdx.x; gid < a.total;
         gid += gridDim.x * blockDim.x) {
        int i = gid;
#pragma unroll
        for (int s = 0; s < 7; s++) {
            if (i < a.n[s]) { a.dst[s][i] = __float2half_rn(a.src[s][i]); break; }
            i -= a.n[s];
        }
    }
}

// ==================== embedding-bag pooling (row-range chunk) ==============
template<typename IT>
__device__ __forceinline__ float4 pool_rows(const IT* __restrict__ idx,
                                            const float* __restrict__ tab,
                                            long long lo, long long hi, int lane) {
    float4 acc = make_float4(0.f, 0.f, 0.f, 0.f);
    long long i = lo;
    for (; i + 4 <= hi; i += 4) {
        size_t r0 = (size_t)idx[i],     r1 = (size_t)idx[i + 1];
        size_t r2 = (size_t)idx[i + 2], r3 = (size_t)idx[i + 3];
        float4 v0 = *(const float4*)(tab + r0 * DEMB + lane * 4);
        float4 v1 = *(const float4*)(tab + r1 * DEMB + lane * 4);
        float4 v2 = *(const float4*)(tab + r2 * DEMB + lane * 4);
        float4 v3 = *(const float4*)(tab + r3 * DEMB + lane * 4);
        acc.x += v0.x + v1.x + v2.x + v3.x;
        acc.y += v0.y + v1.y + v2.y + v3.y;
        acc.z += v0.z + v1.z + v2.z + v3.z;
        acc.w += v0.w + v1.w + v2.w + v3.w;
    }
    for (; i < hi; ++i) {
        float4 v = *(const float4*)(tab + (size_t)idx[i] * DEMB + lane * 4);
        acc.x += v.x; acc.y += v.y; acc.z += v.z; acc.w += v.w;
    }
    return acc;
}

// pools bags [row0, row0 + HALF_B) for all tables
__global__ void pool_kernel(const void* __restrict__ idxp,
                            const void* __restrict__ offp,
                            const float* __restrict__ tables,
                            float* __restrict__ comb,
                            __half* __restrict__ actA,
                            int row0) {
    int wg   = (blockIdx.x * blockDim.x + threadIdx.x) >> 5;
    int lane = threadIdx.x & 31;
    if (wg >= NTAB * HALF_B) return;
    int t = wg / HALF_B;
    int b = row0 + (wg - t * HALF_B);

    const int is64 = g_is64;
    long long lo, hi;
    if (is64) {
        const long long* off = (const long long*)offp + (size_t)t * BATCH;
        lo = (b == 0) ? 0 : off[b];
        hi = (b == BATCH - 1) ? (long long)NTPER : off[b + 1];
    } else {
        const int* off = (const int*)offp + (size_t)t * BATCH;
        lo = (b == 0) ? 0 : (long long)off[b];
        hi = (b == BATCH - 1) ? (long long)NTPER : (long long)off[b + 1];
    }

    const float* tab = tables + (size_t)t * EROWS * DEMB;
    float4 acc;
    if (is64) acc = pool_rows((const long long*)idxp + (size_t)t * NTPER, tab, lo, hi, lane);
    else      acc = pool_rows((const int*)idxp + (size_t)t * NTPER, tab, lo, hi, lane);

    const int col = (t + 1) * DEMB + lane * 4;
    *(float4*)(comb + (size_t)b * FIN + col) = acc;
    size_t o = (size_t)b * FIN + col;
    half_store2(actA, o,     acc.x, acc.y);
    half_store2(actA, o + 2, acc.z, acc.w);
}

// ==================== mma.sync fp16 GEMM: C = A[M,K] * B[N,K]^T ============
// CTA tile MT x 128 (MT in {128, 64}), BK=64, 3-stage cp.async.
// EPI: 2 = DCN: v = aux*(acc+bias)+xlin -> fp32 Cf AND fp16 Ch
//      3 = fp16 Ch raw
//      4 = relu(acc+bias) -> fp16 Ch
//      6 = relu(acc+bias), dot with w3 (aux), atomicAdd into Cf (pre-init b3)
//      7 = relu(acc+bias) -> fp32 Cf AND fp16 Ch
template<int MT>
__device__ __forceinline__ void load_stage(uint32_t base, int st, int kb,
                                           const char* Ab, const char* Bb,
                                           size_t rstride, int row_r, int c16) {
    const uint32_t stage_bytes = (uint32_t)(MT * 128 + 16384);
    uint32_t sA = base + (uint32_t)st * stage_bytes;
    uint32_t sB = sA + (uint32_t)(MT * 128);
    size_t koff = (size_t)kb * 128 + c16;
#pragma unroll
    for (int j = 0; j < MT / 16; j++) {
        int row = j * 16 + row_r;
        uint32_t so = SWZ((uint32_t)(row * 128 + c16));
        cp16(sA + so, Ab + (size_t)row * rstride + koff);
    }
#pragma unroll
    for (int j = 0; j < 8; j++) {
        int row = j * 16 + row_r;
        uint32_t so = SWZ((uint32_t)(row * 128 + c16));
        cp16(sB + so, Bb + (size_t)row * rstride + koff);
    }
}

template<int EPI, int MT>
__global__ void __launch_bounds__(128, (MT == 64) ? 3 : 2)
tc_gemm(const __half* __restrict__ A, const __half* __restrict__ B,
        const float* __restrict__ bias,
        float* __restrict__ Cf, int ldc,
        __half* __restrict__ Ch, int ldh, int K,
        const float* __restrict__ aux, const float* __restrict__ xlin) {
    extern __shared__ char dsm[];
    const uint32_t base = (smem_u32(dsm) + 1023u) & ~1023u;
    constexpr int FM = MT / 32;

    const int tid  = threadIdx.x;
    const int wid  = tid >> 5, lane = tid & 31;
    const int wm   = wid & 1;
    const int wn   = wid >> 1;
    const int m0   = blockIdx.y * MT, n0 = blockIdx.x * 128;
    const int row_r = tid >> 3, c16 = (tid & 7) * 16;
    const uint32_t stage_bytes = (uint32_t)(MT * 128 + 16384);

    const int NKB = K >> 6;
    const char* Ab = (const char*)A + (size_t)m0 * K * 2;
    const char* Bb = (const char*)B + (size_t)n0 * K * 2;
    const size_t rstride = (size_t)K * 2;

    const int ar = lane & 15;
    const int ac = (lane >> 4) * 16;
    const int br = lane & 7;
    const int bn = ((lane >> 4) & 1) * 8;
    const int bc = ((lane >> 3) & 1) * 16;

    float acc[FM][8][4];
#pragma unroll
    for (int i = 0; i < FM; i++)
#pragma unroll
        for (int j = 0; j < 8; j++)
#pragma unroll
            for (int e = 0; e < 4; e++) acc[i][j][e] = 0.f;

    for (int s = 0; s < STAGES - 1 && s < NKB; s++) {
        load_stage<MT>(base, s, s, Ab, Bb, rstride, row_r, c16);
        cp_commit();
    }

    for (int kb = 0; kb < NKB; kb++) {
        const int st = kb % STAGES;
        cp_wait<STAGES - 2>();
        __syncthreads();

        const uint32_t sA = base + (uint32_t)st * stage_bytes;
        const uint32_t sB = sA + (uint32_t)(MT * 128);
#pragma unroll
        for (int ks = 0; ks < 4; ks++) {
            const int kbyte = ks * 32;
            uint32_t a[FM][4];
#pragma unroll
            for (int fm = 0; fm < FM; fm++) {
                uint32_t ad = sA + SWZ((uint32_t)((wm * (MT / 2) + fm * 16 + ar) * 128 + kbyte + ac));
                ldm_x4(a[fm][0], a[fm][1], a[fm][2], a[fm][3], ad);
            }
#pragma unroll
            for (int g = 0; g < 4; g++) {
                uint32_t b0, b1, b2, b3;
                uint32_t bd = sB + SWZ((uint32_t)((wn * 64 + g * 16 + bn + br) * 128 + kbyte + bc));
                ldm_x4(b0, b1, b2, b3, bd);
#pragma unroll
                for (int fm = 0; fm < FM; fm++) {
                    mma16816(acc[fm][2 * g],     a[fm], b0, b1);
                    mma16816(acc[fm][2 * g + 1], a[fm], b2, b3);
                }
            }
        }
        const int nk = kb + STAGES - 1;
        if (nk < NKB)
            load_stage<MT>(base, nk % STAGES, nk, Ab, Bb, rstride, row_r, c16);
        cp_commit();
    }

    // ---------------- epilogue (register accumulators) ----------------
    const int er = lane >> 2;
    const int ec = (lane & 3) * 2;
    float fs[FM][2];
    if (EPI == 6) {
#pragma unroll
        for (int i = 0; i < FM; i++) { fs[i][0] = 0.f; fs[i][1] = 0.f; }
    }
#pragma unroll
    for (int fm = 0; fm < FM; fm++) {
#pragma unroll
        for (int fn = 0; fn < 8; fn++) {
            const int ng = n0 + wn * 64 + fn * 8 + ec;
#pragma unroll
            for (int rr = 0; rr < 2; rr++) {
                const int m = m0 + wm * (MT / 2) + fm * 16 + er + rr * 8;
                float v0 = acc[fm][fn][rr * 2 + 0];
                float v1 = acc[fm][fn][rr * 2 + 1];
                if (EPI == 4 || EPI == 6 || EPI == 7) {
                    v0 += bias[ng];     v0 = v0 > 0.f ? v0 : 0.f;
                    v1 += bias[ng + 1]; v1 = v1 > 0.f ? v1 : 0.f;
                }
                if (EPI == 2) {
                    size_t o = (size_t)m * ldc + ng;
                    float2 cb = *(const float2*)(aux + o);
                    float2 xb = *(const float2*)(xlin + o);
                    v0 = cb.x * (v0 + bias[ng])     + xb.x;
                    v1 = cb.y * (v1 + bias[ng + 1]) + xb.y;
                    *(float2*)(Cf + o) = make_float2(v0, v1);
                }
                if (EPI == 7)
                    *(float2*)(Cf + (size_t)m * ldc + ng) = make_float2(v0, v1);
                if (EPI == 6)
                    fs[fm][rr] += v0 * aux[ng] + v1 * aux[ng + 1];
                if (EPI == 2 || EPI == 3 || EPI == 4 || EPI == 7)
                    half_store2(Ch, (size_t)m * ldh + ng, v0, v1);
            }
        }
    }
    if (EPI == 6) {
#pragma unroll
        for (int fm = 0; fm < FM; fm++)
#pragma unroll
            for (int rr = 0; rr < 2; rr++) {
                float s = fs[fm][rr];
                s += __shfl_xor_sync(0xffffffffu, s, 1);
                s += __shfl_xor_sync(0xffffffffu, s, 2);
                if ((lane & 3) == 0) {
                    const int m = m0 + wm * (MT / 2) + fm * 16 + er + rr * 8;
                    atomicAdd(&Cf[m], s);
                }
            }
    }
}

// ==================== fp32 SGEMM (bottom layer 1 only, K=13) ===============
__global__ void __launch_bounds__(256, 2)
sgemm_l1(const float* __restrict__ A, int lda,
         const float* __restrict__ Bm, int ldb,
         const float* __restrict__ bias,
         int ldc, int K,
         __half* __restrict__ Ch) {
    __shared__ __align__(16) float As[8][128];
    __shared__ __align__(16) float Bs[8][128];
    const int tid = threadIdx.x;
    const int m0 = blockIdx.y * 128, n0 = blockIdx.x * 128;
    const int lr = tid >> 1, lc = (tid & 1) * 4;
    const float* Ag = A + (size_t)(m0 + lr) * lda + lc;
    const float* Bg = Bm + (size_t)(n0 + lr) * ldb + lc;
    const int ty = tid >> 4, tx = tid & 15;

    float acc[8][8];
#pragma unroll
    for (int i = 0; i < 8; i++)
#pragma unroll
        for (int j = 0; j < 8; j++) acc[i][j] = 0.f;

    for (int k0 = 0; k0 < K; k0 += 8) {
#pragma unroll
        for (int j = 0; j < 4; j++) {
            int kk = k0 + lc + j;
            As[lc + j][lr] = (kk < K) ? Ag[k0 + j] : 0.f;
            Bs[lc + j][lr] = (kk < K) ? Bg[k0 + j] : 0.f;
        }
        __syncthreads();
#pragma unroll
        for (int k = 0; k < 8; k++) {
            float4 a0 = *(const float4*)&As[k][ty * 4];
            float4 a1 = *(const float4*)&As[k][64 + ty * 4];
            float4 b0 = *(const float4*)&Bs[k][tx * 4];
            float4 b1 = *(const float4*)&Bs[k][64 + tx * 4];
            float af[8] = {a0.x, a0.y, a0.z, a0.w, a1.x, a1.y, a1.z, a1.w};
            float bf[8] = {b0.x, b0.y, b0.z, b0.w, b1.x, b1.y, b1.z, b1.w};
#pragma unroll
            for (int i = 0; i < 8; i++)
#pragma unroll
                for (int j = 0; j < 8; j++) acc[i][j] += af[i] * bf[j];
        }
        __syncthreads();
    }
#pragma unroll
    for (int i = 0; i < 8; i++) {
        int mg = m0 + ((i < 4) ? (ty * 4 + i) : (64 + ty * 4 + (i - 4)));
        size_t rowoff = (size_t)mg * ldc;
#pragma unroll
        for (int j = 0; j < 8; j++) {
            int ng = n0 + ((j < 4) ? (tx * 4 + j) : (64 + tx * 4 + (j - 4)));
            float v = acc[i][j] + bias[ng];
            v = v > 0.f ? v : 0.f;
            Ch[rowoff + ng] = __float2half_rn(v);
        }
    }
}

// ==================== launch ====================
extern "C" void kernel_launch(void* const* d_in, const int* in_sizes, int n_in,
                              void* d_out, int out_size) {
    const float* dense   = (const float*)d_in[0];
    const void*  indices = d_in[1];
    const void*  offsets = d_in[2];
    const float* emb     = (const float*)d_in[3];
    const float* bW0 = (const float*)d_in[4];  const float* bb0 = (const float*)d_in[5];
    const float* bW1 = (const float*)d_in[6];  const float* bb1 = (const float*)d_in[7];
    const float* bW2 = (const float*)d_in[8];  const float* bb2 = (const float*)d_in[9];
    const float* dcnW = (const float*)d_in[10];
    const float* dcnV = (const float*)d_in[11];
    const float* dcnb = (const float*)d_in[12];
    const float* tW0 = (const float*)d_in[13]; const float* tb0 = (const float*)d_in[14];
    const float* tW1 = (const float*)d_in[15]; const float* tb1 = (const float*)d_in[16];
    const float* tW2 = (const float*)d_in[17]; const float* tb2 = (const float*)d_in[18];
    const float* tW3 = (const float*)d_in[19]; const float* tb3 = (const float*)d_in[20];

    float *comb, *xl;
    __half *actA, *z0h, *z1h, *xvh, *wV, *wW, *wT0, *wT1, *wT2, *wB1, *wB2;
    cudaGetSymbolAddress((void**)&comb, g_comb);
    cudaGetSymbolAddress((void**)&xl,   g_xl);
    cudaGetSymbolAddress((void**)&actA, g_actA);
    cudaGetSymbolAddress((void**)&z0h,  g_z0h);
    cudaGetSymbolAddress((void**)&z1h,  g_z1h);
    cudaGetSymbolAddress((void**)&xvh,  g_xvh);
    cudaGetSymbolAddress((void**)&wV,   g_wV);
    cudaGetSymbolAddress((void**)&wW,   g_wW);
    cudaGetSymbolAddress((void**)&wT0,  g_wT0);
    cudaGetSymbolAddress((void**)&wT1,  g_wT1);
    cudaGetSymbolAddress((void**)&wT2,  g_wT2);
    cudaGetSymbolAddress((void**)&wB1,  g_wB1);
    cudaGetSymbolAddress((void**)&wB2,  g_wB2);

    const int dynsmem128 = STAGES * 32768 + 1024;
    const int dynsmem64  = STAGES * 24576 + 1024;
    cudaFuncSetAttribute(tc_gemm<2,128>, cudaFuncAttributeMaxDynamicSharedMemorySize, dynsmem128);
    cudaFuncSetAttribute(tc_gemm<3,64>,  cudaFuncAttributeMaxDynamicSharedMemorySize, dynsmem64);
    cudaFuncSetAttribute(tc_gemm<4,128>, cudaFuncAttributeMaxDynamicSharedMemorySize, dynsmem128);
    cudaFuncSetAttribute(tc_gemm<6,64>,  cudaFuncAttributeMaxDynamicSharedMemorySize, dynsmem64);
    cudaFuncSetAttribute(tc_gemm<7,128>, cudaFuncAttributeMaxDynamicSharedMemorySize, dynsmem128);

    cudaStream_t s1;
    cudaEvent_t evFork, evJoin, evP0, evB;
    cudaStreamCreateWithFlags(&s1, cudaStreamNonBlocking);
    cudaEventCreateWithFlags(&evFork, cudaEventDisableTiming);
    cudaEventCreateWithFlags(&evJoin, cudaEventDisableTiming);
    cudaEventCreateWithFlags(&evP0,   cudaEventDisableTiming);
    cudaEventCreateWithFlags(&evB,    cudaEventDisableTiming);

    cudaEventRecord(evFork, 0);
    cudaStreamWaitEvent(s1, evFork, 0);

    // s1: weight conversion + out-init, then bottom MLP into comb/actA cols 0-127
    ConvArgs ca;
    ca.src[0] = dcnV; ca.dst[0] = wV;  ca.n[0] = 3 * LOWR * FIN;
    ca.src[1] = dcnW; ca.dst[1] = wW;  ca.n[1] = 3 * FIN * LOWR;
    ca.src[2] = tW0;  ca.dst[2] = wT0; ca.n[2] = 1024 * FIN;
    ca.src[3] = tW1;  ca.dst[3] = wT1; ca.n[3] = 1024 * 1024;
    ca.src[4] = tW2;  ca.dst[4] = wT2; ca.n[4] = 512 * 1024;
    ca.src[5] = bW1;  ca.dst[5] = wB1; ca.n[5] = 256 * 512;
    ca.src[6] = bW2;  ca.dst[6] = wB2; ca.n[6] = 128 * 256;
    ca.total = ca.n[0] + ca.n[1] + ca.n[2] + ca.n[3] + ca.n[4] + ca.n[5] + ca.n[6];
    ca.out = (float*)d_out;
    ca.b3 = tb3;
    conv_kernel<<<2048, 256, 0, s1>>>(ca);
    sgemm_l1<<<dim3(4, 32), 256, 0, s1>>>(dense, 13, bW0, 13, bb0, 512, 13, z0h);
    tc_gemm<4,128><<<dim3(2, 32), 128, dynsmem128, s1>>>(
        z0h, wB1, bb1, nullptr, 0, z1h, 256, 512, nullptr, nullptr);
    tc_gemm<7,128><<<dim3(1, 32), 128, dynsmem128, s1>>>(
        z1h, wB2, bb2, comb, FIN, actA, FIN, 256, nullptr, nullptr);
    cudaEventRecord(evJoin, s1);

    // main stream: dtype detect, then pooling in two half-batch chunks
    detect_kernel<<<1, 256>>>((const unsigned*)offsets, in_sizes[2]);
    pool_kernel<<<(NTAB * HALF_B) / 8, 256>>>(indices, offsets, emb, comb, actA, 0);
    cudaEventRecord(evP0, 0);
    pool_kernel<<<(NTAB * HALF_B) / 8, 256>>>(indices, offsets, emb, comb, actA, HALF_B);

    // chain-0 on s1: needs bottom chain (stream order) + pool chunk 0
    cudaStreamWaitEvent(s1, evP0, 0);
    // chain-1 on main: needs pool chunk 1 (stream order) + bottom chain
    cudaStreamWaitEvent(0, evJoin, 0);

    for (int c = 0; c < 2; c++) {
        cudaStream_t st = (c == 0) ? s1 : (cudaStream_t)0;
        const size_t ro = (size_t)c * HALF_B;   // row offset
        __half* cA  = actA + ro * FIN;
        __half* cXv = xvh  + ro * LOWR;
        float*  cXl = xl   + ro * FIN;
        float*  cCb = comb + ro * FIN;
        __half* cZ0 = z0h  + ro * 1024;
        __half* cZ1 = z1h  + ro * 1024;
        float*  cOut = (float*)d_out + ro;

        // low-rank DCN
        for (int l = 0; l < 3; l++) {
            const float* xlin = (l == 0) ? cCb : cXl;
            tc_gemm<3,64><<<dim3(LOWR / 128, HALF_B / 64), 128, dynsmem64, st>>>(
                cA, wV + (size_t)l * LOWR * FIN, nullptr, nullptr, 0,
                cXv, LOWR, FIN, nullptr, nullptr);
            tc_gemm<2,128><<<dim3(FIN / 128, HALF_B / 128), 128, dynsmem128, st>>>(
                cXv, wW + (size_t)l * FIN * LOWR, dcnb + (size_t)l * FIN, cXl, FIN,
                cA, FIN, LOWR, cCb, xlin);
        }

        // top MLP: 3456 -> 1024 -> 1024 -> 512 (relu) -> 1 (fused dot)
        tc_gemm<4,128><<<dim3(8, HALF_B / 128), 128, dynsmem128, st>>>(
            cA, wT0, tb0, nullptr, 0, cZ0, 1024, FIN, nullptr, nullptr);
        tc_gemm<4,128><<<dim3(8, HALF_B / 128), 128, dynsmem128, st>>>(
            cZ0, wT1, tb1, nullptr, 0, cZ1, 1024, 1024, nullptr, nullptr);
        tc_gemm<6,64><<<dim3(4, HALF_B / 64), 128, dynsmem64, st>>>(
            cZ1, wT2, tb2, cOut, 0, nullptr, 0, 1024, tW3, nullptr);
    }

    // final join so the captured graph ends with both chains complete
    cudaEventRecord(evB, s1);
    cudaStreamWaitEvent(0, evB, 0);
}

// round 17
// speedup vs baseline: 1.1007x; 1.1007x over previous
#include <cuda_runtime.h>
#include <cuda_fp16.h>
#include <cstdint>
#include <cstddef>

// ---------------- problem constants ----------------
#define BATCH   4096
#define NTAB    26
#define DEMB    128
#define NTPER   81920
#define EROWS   100000
#define FIN     3456
#define LOWR    512
#define STAGES  3

// ---------------- scratch (device globals; no runtime alloc) ----------------
__device__ float  g_comb[BATCH * FIN];     // combined features (fp32, immutable)
__device__ float  g_xl  [BATCH * FIN];     // DCN running state (fp32 master)
__device__ int    g_is64;
__device__ __half g_actA[BATCH * FIN];     // fp16 copy of current DCN input
__device__ __half g_z0h [BATCH * 1024];    // also bot0h (disjoint in time)
__device__ __half g_z1h [BATCH * 1024];    // also bot1h
__device__ __half g_xvh [BATCH * LOWR];
// dedicated fp16 weight buffers
__device__ __half g_wV [3 * LOWR * FIN];
__device__ __half g_wW [3 * FIN * LOWR];
__device__ __half g_wT0[1024 * FIN];
__device__ __half g_wT1[1024 * 1024];
__device__ __half g_wT2[512 * 1024];
__device__ __half g_wB1[256 * 512];
__device__ __half g_wB2[128 * 256];

// ==================== PTX helpers ====================
__device__ __forceinline__ uint32_t smem_u32(const void* p) {
    uint32_t a;
    asm("{ .reg .u64 t; cvta.to.shared.u64 t, %1; cvt.u32.u64 %0, t; }" : "=r"(a) : "l"(p));
    return a;
}
#define SWZ(x) ((x) ^ (((x) >> 3) & 0x70))

__device__ __forceinline__ void cp16(uint32_t dst, const void* src) {
    asm volatile("cp.async.cg.shared.global [%0], [%1], 16;" :: "r"(dst), "l"(src) : "memory");
}
__device__ __forceinline__ void cp_commit() { asm volatile("cp.async.commit_group;" ::: "memory"); }
template<int N> __device__ __forceinline__ void cp_wait() {
    asm volatile("cp.async.wait_group %0;" :: "n"(N) : "memory");
}
__device__ __forceinline__ void ldm_x4(uint32_t& r0, uint32_t& r1, uint32_t& r2, uint32_t& r3,
                                       uint32_t addr) {
    asm volatile("ldmatrix.sync.aligned.m8n8.x4.shared.b16 {%0,%1,%2,%3}, [%4];"
                 : "=r"(r0), "=r"(r1), "=r"(r2), "=r"(r3) : "r"(addr));
}
__device__ __forceinline__ void mma16816(float* c, const uint32_t* a, uint32_t b0, uint32_t b1) {
    asm volatile(
        "mma.sync.aligned.m16n8k16.row.col.f32.f16.f16.f32 "
        "{%0,%1,%2,%3}, {%4,%5,%6,%7}, {%8,%9}, {%0,%1,%2,%3};"
        : "+f"(c[0]), "+f"(c[1]), "+f"(c[2]), "+f"(c[3])
        : "r"(a[0]), "r"(a[1]), "r"(a[2]), "r"(a[3]), "r"(b0), "r"(b1));
}

__device__ __forceinline__ void half_store2(__half* __restrict__ p, size_t o,
                                            float v0, float v1) {
    __half2 hh; hh.x = __float2half_rn(v0); hh.y = __float2half_rn(v1);
    *(__half2*)(p + o) = hh;
}

// ==================== dtype detection (int64 vs int32) ====================
__global__ void detect_kernel(const unsigned* __restrict__ words, int n_elems) {
    __shared__ unsigned red;
    if (threadIdx.x == 0) red = 0u;
    __syncthreads();
    int n = n_elems < 8192 ? n_elems : 8192;
    unsigned acc = 0u;
    for (int i = 1 + 2 * (int)threadIdx.x; i < n; i += 2 * (int)blockDim.x) acc |= words[i];
    if (acc) atomicOr(&red, 1u);
    __syncthreads();
    if (threadIdx.x == 0) g_is64 = (red == 0u) ? 1 : 0;
}

// ==================== fused weight conversion + out-init ===================
struct ConvArgs {
    const float* src[7];
    __half*      dst[7];
    int          n[7];
    int          total;
    float*       out;       // d_out, init to b3[0]
    const float* b3;
};

__global__ void conv_kernel(ConvArgs a) {
    if (blockIdx.x == 0) {   // init final output to bias b3
        float b = a.b3[0];
        for (int i = threadIdx.x; i < BATCH; i += blockDim.x) a.out[i] = b;
    }
    for (int gid = blockIdx.x * blockDim.x + threadIdx.x; gid < a.total;
         gid += gridDim.x * blockDim.x) {
        int i = gid;
#pragma unroll
        for (int s = 0; s < 7; s++) {
            if (i < a.n[s]) { a.dst[s][i] = __float2half_rn(a.src[s][i]); break; }
            i -= a.n[s];
        }
    }
}

// ==================== embedding-bag pooling: one warp per (table, bag) ======
// 8-wide unrolled gather for deeper MLP (hides 577-cyc DRAM latency).
template<typename IT>
__device__ __forceinline__ float4 pool_rows(const IT* __restrict__ idx,
                                            const float* __restrict__ tab,
                                            long long lo, long long hi, int lane) {
    float4 acc = make_float4(0.f, 0.f, 0.f, 0.f);
    long long i = lo;
    for (; i + 8 <= hi; i += 8) {
        const float* p0 = tab + (size_t)idx[i]     * DEMB + lane * 4;
        const float* p1 = tab + (size_t)idx[i + 1] * DEMB + lane * 4;
        const float* p2 = tab + (size_t)idx[i + 2] * DEMB + lane * 4;
        const float* p3 = tab + (size_t)idx[i + 3] * DEMB + lane * 4;
        const float* p4 = tab + (size_t)idx[i + 4] * DEMB + lane * 4;
        const float* p5 = tab + (size_t)idx[i + 5] * DEMB + lane * 4;
        const float* p6 = tab + (size_t)idx[i + 6] * DEMB + lane * 4;
        const float* p7 = tab + (size_t)idx[i + 7] * DEMB + lane * 4;
        float4 v0 = *(const float4*)p0, v1 = *(const float4*)p1;
        float4 v2 = *(const float4*)p2, v3 = *(const float4*)p3;
        float4 v4 = *(const float4*)p4, v5 = *(const float4*)p5;
        float4 v6 = *(const float4*)p6, v7 = *(const float4*)p7;
        acc.x += (v0.x + v1.x) + (v2.x + v3.x) + (v4.x + v5.x) + (v6.x + v7.x);
        acc.y += (v0.y + v1.y) + (v2.y + v3.y) + (v4.y + v5.y) + (v6.y + v7.y);
        acc.z += (v0.z + v1.z) + (v2.z + v3.z) + (v4.z + v5.z) + (v6.z + v7.z);
        acc.w += (v0.w + v1.w) + (v2.w + v3.w) + (v4.w + v5.w) + (v6.w + v7.w);
    }
    for (; i + 4 <= hi; i += 4) {
        float4 v0 = *(const float4*)(tab + (size_t)idx[i]     * DEMB + lane * 4);
        float4 v1 = *(const float4*)(tab + (size_t)idx[i + 1] * DEMB + lane * 4);
        float4 v2 = *(const float4*)(tab + (size_t)idx[i + 2] * DEMB + lane * 4);
        float4 v3 = *(const float4*)(tab + (size_t)idx[i + 3] * DEMB + lane * 4);
        acc.x += v0.x + v1.x + v2.x + v3.x;
        acc.y += v0.y + v1.y + v2.y + v3.y;
        acc.z += v0.z + v1.z + v2.z + v3.z;
        acc.w += v0.w + v1.w + v2.w + v3.w;
    }
    for (; i < hi; ++i) {
        float4 v = *(const float4*)(tab + (size_t)idx[i] * DEMB + lane * 4);
        acc.x += v.x; acc.y += v.y; acc.z += v.z; acc.w += v.w;
    }
    return acc;
}

__global__ void pool_kernel(const void* __restrict__ idxp,
                            const void* __restrict__ offp,
                            const float* __restrict__ tables,
                            float* __restrict__ comb,
                            __half* __restrict__ actA) {
    int wg   = (blockIdx.x * blockDim.x + threadIdx.x) >> 5;
    int lane = threadIdx.x & 31;
    if (wg >= NTAB * BATCH) return;
    int t = wg / BATCH;
    int b = wg - t * BATCH;

    const int is64 = g_is64;
    long long lo, hi;
    if (is64) {
        const long long* off = (const long long*)offp + (size_t)t * BATCH;
        lo = (b == 0) ? 0 : off[b];
        hi = (b == BATCH - 1) ? (long long)NTPER : off[b + 1];
    } else {
        const int* off = (const int*)offp + (size_t)t * BATCH;
        lo = (b == 0) ? 0 : (long long)off[b];
        hi = (b == BATCH - 1) ? (long long)NTPER : (long long)off[b + 1];
    }

    const float* tab = tables + (size_t)t * EROWS * DEMB;
    float4 acc;
    if (is64) acc = pool_rows((const long long*)idxp + (size_t)t * NTPER, tab, lo, hi, lane);
    else      acc = pool_rows((const int*)idxp + (size_t)t * NTPER, tab, lo, hi, lane);

    const int col = (t + 1) * DEMB + lane * 4;
    *(float4*)(comb + (size_t)b * FIN + col) = acc;
    size_t o = (size_t)b * FIN + col;
    half_store2(actA, o,     acc.x, acc.y);
    half_store2(actA, o + 2, acc.z, acc.w);
}

// ==================== mma.sync fp16 GEMM: C = A[M,K] * B[N,K]^T ============
// CTA tile MT x 128 (MT in {128, 64}), BK=64, 3-stage cp.async.
// MT=128: 2 CTA/SM, warp tile 64x64.  MT=64: 3 CTA/SM, warp tile 32x64.
// EPI: 2 = DCN: v = aux*(acc+bias)+xlin -> fp32 Cf AND fp16 Ch
//          (xlin == aux allowed: comb reused, duplicate read elided)
//      3 = fp16 Ch raw
//      4 = relu(acc+bias) -> fp16 Ch
//      6 = relu(acc+bias), dot with w3 (aux), atomicAdd into Cf (pre-init b3)
//      7 = relu(acc+bias) -> fp32 Cf AND fp16 Ch
template<int MT>
__device__ __forceinline__ void load_stage(uint32_t base, int st, int kb,
                                           const char* Ab, const char* Bb,
                                           size_t rstride, int row_r, int c16) {
    const uint32_t stage_bytes = (uint32_t)(MT * 128 + 16384);
    uint32_t sA = base + (uint32_t)st * stage_bytes;
    uint32_t sB = sA + (uint32_t)(MT * 128);
    size_t koff = (size_t)kb * 128 + c16;
#pragma unroll
    for (int j = 0; j < MT / 16; j++) {
        int row = j * 16 + row_r;
        uint32_t so = SWZ((uint32_t)(row * 128 + c16));
        cp16(sA + so, Ab + (size_t)row * rstride + koff);
    }
#pragma unroll
    for (int j = 0; j < 8; j++) {
        int row = j * 16 + row_r;
        uint32_t so = SWZ((uint32_t)(row * 128 + c16));
        cp16(sB + so, Bb + (size_t)row * rstride + koff);
    }
}

template<int EPI, int MT>
__global__ void __launch_bounds__(128, (MT == 64) ? 3 : 2)
tc_gemm(const __half* __restrict__ A, const __half* __restrict__ B,
        const float* __restrict__ bias,
        float* __restrict__ Cf, int ldc,
        __half* __restrict__ Ch, int ldh, int K,
        const float* __restrict__ aux, const float* __restrict__ xlin) {
    extern __shared__ char dsm[];
    const uint32_t base = (smem_u32(dsm) + 1023u) & ~1023u;
    constexpr int FM = MT / 32;

    const int tid  = threadIdx.x;
    const int wid  = tid >> 5, lane = tid & 31;
    const int wm   = wid & 1;
    const int wn   = wid >> 1;
    const int m0   = blockIdx.y * MT, n0 = blockIdx.x * 128;
    const int row_r = tid >> 3, c16 = (tid & 7) * 16;
    const uint32_t stage_bytes = (uint32_t)(MT * 128 + 16384);

    const int NKB = K >> 6;
    const char* Ab = (const char*)A + (size_t)m0 * K * 2;
    const char* Bb = (const char*)B + (size_t)n0 * K * 2;
    const size_t rstride = (size_t)K * 2;

    const int ar = lane & 15;
    const int ac = (lane >> 4) * 16;
    const int br = lane & 7;
    const int bn = ((lane >> 4) & 1) * 8;
    const int bc = ((lane >> 3) & 1) * 16;

    float acc[FM][8][4];
#pragma unroll
    for (int i = 0; i < FM; i++)
#pragma unroll
        for (int j = 0; j < 8; j++)
#pragma unroll
            for (int e = 0; e < 4; e++) acc[i][j][e] = 0.f;

    for (int s = 0; s < STAGES - 1 && s < NKB; s++) {
        load_stage<MT>(base, s, s, Ab, Bb, rstride, row_r, c16);
        cp_commit();
    }

    for (int kb = 0; kb < NKB; kb++) {
        const int st = kb % STAGES;
        cp_wait<STAGES - 2>();
        __syncthreads();

        const uint32_t sA = base + (uint32_t)st * stage_bytes;
        const uint32_t sB = sA + (uint32_t)(MT * 128);
#pragma unroll
        for (int ks = 0; ks < 4; ks++) {
            const int kbyte = ks * 32;
            uint32_t a[FM][4];
#pragma unroll
            for (int fm = 0; fm < FM; fm++) {
                uint32_t ad = sA + SWZ((uint32_t)((wm * (MT / 2) + fm * 16 + ar) * 128 + kbyte + ac));
                ldm_x4(a[fm][0], a[fm][1], a[fm][2], a[fm][3], ad);
            }
#pragma unroll
            for (int g = 0; g < 4; g++) {
                uint32_t b0, b1, b2, b3;
                uint32_t bd = sB + SWZ((uint32_t)((wn * 64 + g * 16 + bn + br) * 128 + kbyte + bc));
                ldm_x4(b0, b1, b2, b3, bd);
#pragma unroll
                for (int fm = 0; fm < FM; fm++) {
                    mma16816(acc[fm][2 * g],     a[fm], b0, b1);
                    mma16816(acc[fm][2 * g + 1], a[fm], b2, b3);
                }
            }
        }
        // slot refilled below was consumed last iteration; fenced by the
        // post-wait __syncthreads() above.
        const int nk = kb + STAGES - 1;
        if (nk < NKB)
            load_stage<MT>(base, nk % STAGES, nk, Ab, Bb, rstride, row_r, c16);
        cp_commit();
    }

    // ---------------- epilogue (register accumulators) ----------------
    const int er = lane >> 2;
    const int ec = (lane & 3) * 2;
    const bool xl_same = (EPI == 2) && (xlin == aux);
    float fs[FM][2];
    if (EPI == 6) {
#pragma unroll
        for (int i = 0; i < FM; i++) { fs[i][0] = 0.f; fs[i][1] = 0.f; }
    }
#pragma unroll
    for (int fm = 0; fm < FM; fm++) {
#pragma unroll
        for (int fn = 0; fn < 8; fn++) {
            const int ng = n0 + wn * 64 + fn * 8 + ec;
#pragma unroll
            for (int rr = 0; rr < 2; rr++) {
                const int m = m0 + wm * (MT / 2) + fm * 16 + er + rr * 8;
                float v0 = acc[fm][fn][rr * 2 + 0];
                float v1 = acc[fm][fn][rr * 2 + 1];
                if (EPI == 4 || EPI == 6 || EPI == 7) {
                    v0 += bias[ng];     v0 = v0 > 0.f ? v0 : 0.f;
                    v1 += bias[ng + 1]; v1 = v1 > 0.f ? v1 : 0.f;
                }
                if (EPI == 2) {
                    size_t o = (size_t)m * ldc + ng;
                    float2 cb = *(const float2*)(aux + o);
                    float2 xb = xl_same ? cb : *(const float2*)(xlin + o);
                    v0 = cb.x * (v0 + bias[ng])     + xb.x;
                    v1 = cb.y * (v1 + bias[ng + 1]) + xb.y;
                    *(float2*)(Cf + o) = make_float2(v0, v1);
                }
                if (EPI == 7)
                    *(float2*)(Cf + (size_t)m * ldc + ng) = make_float2(v0, v1);
                if (EPI == 6)
                    fs[fm][rr] += v0 * aux[ng] + v1 * aux[ng + 1];
                if (EPI == 2 || EPI == 3 || EPI == 4 || EPI == 7)
                    half_store2(Ch, (size_t)m * ldh + ng, v0, v1);
            }
        }
    }
    if (EPI == 6) {
#pragma unroll
        for (int fm = 0; fm < FM; fm++)
#pragma unroll
            for (int rr = 0; rr < 2; rr++) {
                float s = fs[fm][rr];
                s += __shfl_xor_sync(0xffffffffu, s, 1);
                s += __shfl_xor_sync(0xffffffffu, s, 2);
                if ((lane & 3) == 0) {
                    const int m = m0 + wm * (MT / 2) + fm * 16 + er + rr * 8;
                    atomicAdd(&Cf[m], s);
                }
            }
    }
}

// ==================== fp32 SGEMM (bottom layer 1 only, K=13) ===============
__global__ void __launch_bounds__(256, 2)
sgemm_l1(const float* __restrict__ A, int lda,
         const float* __restrict__ Bm, int ldb,
         const float* __restrict__ bias,
         int ldc, int K,
         __half* __restrict__ Ch) {
    __shared__ __align__(16) float As[8][128];
    __shared__ __align__(16) float Bs[8][128];
    const int tid = threadIdx.x;
    const int m0 = blockIdx.y * 128, n0 = blockIdx.x * 128;
    const int lr = tid >> 1, lc = (tid & 1) * 4;
    const float* Ag = A + (size_t)(m0 + lr) * lda + lc;
    const float* Bg = Bm + (size_t)(n0 + lr) * ldb + lc;
    const int ty = tid >> 4, tx = tid & 15;

    float acc[8][8];
#pragma unroll
    for (int i = 0; i < 8; i++)
#pragma unroll
        for (int j = 0; j < 8; j++) acc[i][j] = 0.f;

    for (int k0 = 0; k0 < K; k0 += 8) {
#pragma unroll
        for (int j = 0; j < 4; j++) {
            int kk = k0 + lc + j;
            As[lc + j][lr] = (kk < K) ? Ag[k0 + j] : 0.f;
            Bs[lc + j][lr] = (kk < K) ? Bg[k0 + j] : 0.f;
        }
        __syncthreads();
#pragma unroll
        for (int k = 0; k < 8; k++) {
            float4 a0 = *(const float4*)&As[k][ty * 4];
            float4 a1 = *(const float4*)&As[k][64 + ty * 4];
            float4 b0 = *(const float4*)&Bs[k][tx * 4];
            float4 b1 = *(const float4*)&Bs[k][64 + tx * 4];
            float af[8] = {a0.x, a0.y, a0.z, a0.w, a1.x, a1.y, a1.z, a1.w};
            float bf[8] = {b0.x, b0.y, b0.z, b0.w, b1.x, b1.y, b1.z, b1.w};
#pragma unroll
            for (int i = 0; i < 8; i++)
#pragma unroll
                for (int j = 0; j < 8; j++) acc[i][j] += af[i] * bf[j];
        }
        __syncthreads();
    }
#pragma unroll
    for (int i = 0; i < 8; i++) {
        int mg = m0 + ((i < 4) ? (ty * 4 + i) : (64 + ty * 4 + (i - 4)));
        size_t rowoff = (size_t)mg * ldc;
#pragma unroll
        for (int j = 0; j < 8; j++) {
            int ng = n0 + ((j < 4) ? (tx * 4 + j) : (64 + tx * 4 + (j - 4)));
            float v = acc[i][j] + bias[ng];
            v = v > 0.f ? v : 0.f;
            Ch[rowoff + ng] = __float2half_rn(v);
        }
    }
}

// ==================== launch ====================
extern "C" void kernel_launch(void* const* d_in, const int* in_sizes, int n_in,
                              void* d_out, int out_size) {
    const float* dense   = (const float*)d_in[0];
    const void*  indices = d_in[1];
    const void*  offsets = d_in[2];
    const float* emb     = (const float*)d_in[3];
    const float* bW0 = (const float*)d_in[4];  const float* bb0 = (const float*)d_in[5];
    const float* bW1 = (const float*)d_in[6];  const float* bb1 = (const float*)d_in[7];
    const float* bW2 = (const float*)d_in[8];  const float* bb2 = (const float*)d_in[9];
    const float* dcnW = (const float*)d_in[10];
    const float* dcnV = (const float*)d_in[11];
    const float* dcnb = (const float*)d_in[12];
    const float* tW0 = (const float*)d_in[13]; const float* tb0 = (const float*)d_in[14];
    const float* tW1 = (const float*)d_in[15]; const float* tb1 = (const float*)d_in[16];
    const float* tW2 = (const float*)d_in[17]; const float* tb2 = (const float*)d_in[18];
    const float* tW3 = (const float*)d_in[19]; const float* tb3 = (const float*)d_in[20];

    float *comb, *xl;
    __half *actA, *z0h, *z1h, *xvh, *wV, *wW, *wT0, *wT1, *wT2, *wB1, *wB2;
    cudaGetSymbolAddress((void**)&comb, g_comb);
    cudaGetSymbolAddress((void**)&xl,   g_xl);
    cudaGetSymbolAddress((void**)&actA, g_actA);
    cudaGetSymbolAddress((void**)&z0h,  g_z0h);
    cudaGetSymbolAddress((void**)&z1h,  g_z1h);
    cudaGetSymbolAddress((void**)&xvh,  g_xvh);
    cudaGetSymbolAddress((void**)&wV,   g_wV);
    cudaGetSymbolAddress((void**)&wW,   g_wW);
    cudaGetSymbolAddress((void**)&wT0,  g_wT0);
    cudaGetSymbolAddress((void**)&wT1,  g_wT1);
    cudaGetSymbolAddress((void**)&wT2,  g_wT2);
    cudaGetSymbolAddress((void**)&wB1,  g_wB1);
    cudaGetSymbolAddress((void**)&wB2,  g_wB2);

    const int dynsmem128 = STAGES * 32768 + 1024;
    const int dynsmem64  = STAGES * 24576 + 1024;
    cudaFuncSetAttribute(tc_gemm<2,128>, cudaFuncAttributeMaxDynamicSharedMemorySize, dynsmem128);
    cudaFuncSetAttribute(tc_gemm<3,64>,  cudaFuncAttributeMaxDynamicSharedMemorySize, dynsmem64);
    cudaFuncSetAttribute(tc_gemm<4,128>, cudaFuncAttributeMaxDynamicSharedMemorySize, dynsmem128);
    cudaFuncSetAttribute(tc_gemm<6,64>,  cudaFuncAttributeMaxDynamicSharedMemorySize, dynsmem64);
    cudaFuncSetAttribute(tc_gemm<7,128>, cudaFuncAttributeMaxDynamicSharedMemorySize, dynsmem128);

    cudaStream_t s1;
    cudaEvent_t evFork, evJoin;
    cudaStreamCreateWithFlags(&s1, cudaStreamNonBlocking);
    cudaEventCreateWithFlags(&evFork, cudaEventDisableTiming);
    cudaEventCreateWithFlags(&evJoin, cudaEventDisableTiming);

    cudaEventRecord(evFork, 0);
    cudaStreamWaitEvent(s1, evFork, 0);

    // s1: weight conversion + out-init, then bottom MLP into comb/actA cols 0-127
    ConvArgs ca;
    ca.src[0] = dcnV; ca.dst[0] = wV;  ca.n[0] = 3 * LOWR * FIN;
    ca.src[1] = dcnW; ca.dst[1] = wW;  ca.n[1] = 3 * FIN * LOWR;
    ca.src[2] = tW0;  ca.dst[2] = wT0; ca.n[2] = 1024 * FIN;
    ca.src[3] = tW1;  ca.dst[3] = wT1; ca.n[3] = 1024 * 1024;
    ca.src[4] = tW2;  ca.dst[4] = wT2; ca.n[4] = 512 * 1024;
    ca.src[5] = bW1;  ca.dst[5] = wB1; ca.n[5] = 256 * 512;
    ca.src[6] = bW2;  ca.dst[6] = wB2; ca.n[6] = 128 * 256;
    ca.total = ca.n[0] + ca.n[1] + ca.n[2] + ca.n[3] + ca.n[4] + ca.n[5] + ca.n[6];
    ca.out = (float*)d_out;
    ca.b3 = tb3;
    conv_kernel<<<2048, 256, 0, s1>>>(ca);
    sgemm_l1<<<dim3(4, 32), 256, 0, s1>>>(dense, 13, bW0, 13, bb0, 512, 13, z0h);
    tc_gemm<4,128><<<dim3(2, 32), 128, dynsmem128, s1>>>(
        z0h, wB1, bb1, nullptr, 0, z1h, 256, 512, nullptr, nullptr);
    tc_gemm<7,128><<<dim3(1, 32), 128, dynsmem128, s1>>>(
        z1h, wB2, bb2, comb, FIN, actA, FIN, 256, nullptr, nullptr);
    cudaEventRecord(evJoin, s1);

    // main stream: dtype detect + pooling into comb/actA cols 128..3455
    detect_kernel<<<1, 256>>>((const unsigned*)offsets, in_sizes[2]);
    pool_kernel<<<(NTAB * BATCH) / 8, 256>>>(indices, offsets, emb, comb, actA);

    // join: DCN needs full actA/comb and converted weights
    cudaStreamWaitEvent(0, evJoin, 0);

    // --- low-rank DCN (fp16 GEMMs; x_l master in fp32, fp16 feed in actA)
    for (int l = 0; l < 3; l++) {
        const float* xlin = (l == 0) ? comb : xl;
        tc_gemm<3,64><<<dim3(LOWR / 128, 64), 128, dynsmem64>>>(
            actA, wV + (size_t)l * LOWR * FIN, nullptr, nullptr, 0,
            xvh, LOWR, FIN, nullptr, nullptr);
        tc_gemm<2,128><<<dim3(FIN / 128, 32), 128, dynsmem128>>>(
            xvh, wW + (size_t)l * FIN * LOWR, dcnb + (size_t)l * FIN, xl, FIN,
            actA, FIN, LOWR, comb, xlin);
    }

    // --- top MLP: 3456 -> 1024 -> 1024 -> 512 (relu) -> 1 (fused dot)
    tc_gemm<4,128><<<dim3(8, 32), 128, dynsmem128>>>(
        actA, wT0, tb0, nullptr, 0, z0h, 1024, FIN, nullptr, nullptr);
    tc_gemm<4,128><<<dim3(8, 32), 128, dynsmem128>>>(
        z0h, wT1, tb1, nullptr, 0, z1h, 1024, 1024, nullptr, nullptr);
    tc_gemm<6,64><<<dim3(4, 64), 128, dynsmem64>>>(
        z1h, wT2, tb2, (float*)d_out, 0, nullptr, 0, 1024, tW3, nullptr);
}